// round 12
// baseline (speedup 1.0000x reference)
#include <cuda_runtime.h>
#include <cstdint>

#define NIMG 4
#define PBINS 10
#define LBINS 6
#define NBINS 66                      // 60 inter bins + 6 label-count bins
#define TPB 256
#define NWARPS (TPB/32)               // 8
#define BLOCKS_PER_IMG 148            // 592 blocks = exactly 4 per SM
#define TOTAL_BLOCKS (BLOCKS_PER_IMG * NIMG)
#define VECS_PER_IMG (1024*1024/4)    // 262144 float4 per image
#define STRIDE (BLOCKS_PER_IMG * TPB) // 37888
#define KITERS 7                      // 7*37888 >= 262144 (guarded)

// Global scratch (zero-initialized at module load; every block restores its
// own slice before exit, so graph replays see identical state).
__device__ float g_part[TOTAL_BLOCKS][NBINS];  // per-block exclusive partials
__device__ float g_bins[NIMG][NBINS];
__device__ unsigned int g_ticket;

__global__ void __launch_bounds__(TPB, 4)
sc_fused_kernel(const float* __restrict__ pred,
                const int* __restrict__ pconn,
                const int* __restrict__ lconn,
                float* __restrict__ out) {
    // NO smem histogram: the hot loop scatters via fire-and-forget L2 REDG
    // (red.global.add.f32) into this block's exclusive partial array.
    // SM-side cost is store-issue only; the L2 atomic ALUs do the RMW.
    __shared__ float losses[NIMG];
    __shared__ float binc[NIMG][NBINS];
    __shared__ bool  s_last;

    const int tid  = threadIdx.x;
    const int lane = tid & 31;
    const int img  = blockIdx.y;
    const int bid  = blockIdx.y * BLOCKS_PER_IMG + blockIdx.x;

    float* const mypart = g_part[bid];

    const size_t base = (size_t)img * VECS_PER_IMG;
    const float4* __restrict__ p4  = ((const float4*)pred)  + base;
    const int4*   __restrict__ pc4 = ((const int4*)pconn)   + base;
    const int4*   __restrict__ lc4 = ((const int4*)lconn)   + base;

    // Label counts: 6 byte-fields packed in a 64-bit register.
    // <= 28 pixels/thread -> fields never overflow 8 bits.
    unsigned long long cnt = 0ULL;

    int v = blockIdx.x * TPB + tid;
    #pragma unroll
    for (int k = 0; k < KITERS; k++, v += STRIDE) {
        if (v < VECS_PER_IMG) {
            float4 p = p4[v];
            int4   c = pc4[v];
            int4   l = lc4[v];
            // Return value unused -> compiler emits RED (no scoreboard wait).
            atomicAdd(&mypart[l.x * PBINS + c.x], p.x);
            atomicAdd(&mypart[l.y * PBINS + c.y], p.y);
            atomicAdd(&mypart[l.z * PBINS + c.z], p.z);
            atomicAdd(&mypart[l.w * PBINS + c.w], p.w);
            cnt += (1ULL << (8 * l.x)) + (1ULL << (8 * l.y))
                 + (1ULL << (8 * l.z)) + (1ULL << (8 * l.w));
        }
    }

    // Warp-reduce packed counts (split 8-bit fields into 16-bit-spaced
    // halves so 32-lane sums, <=896, don't overflow), then 6 REDG from lane 0.
    unsigned long long lo = cnt & 0x00FF00FF00FF00FFULL;         // labels 0,2,4
    unsigned long long hi = (cnt >> 8) & 0x00FF00FF00FF00FFULL;  // labels 1,3,5
    #pragma unroll
    for (int d = 16; d > 0; d >>= 1) {
        lo += __shfl_down_sync(0xFFFFFFFFu, lo, d);
        hi += __shfl_down_sync(0xFFFFFFFFu, hi, d);
    }
    if (lane == 0) {
        #pragma unroll
        for (int l = 0; l < 3; l++) {
            atomicAdd(&mypart[60 + 2 * l],     (float)((lo >> (16 * l)) & 0xFFFFULL));
            atomicAdd(&mypart[60 + 2 * l + 1], (float)((hi >> (16 * l)) & 0xFFFFULL));
        }
    }

    // Make this block's REDGs visible to its own readback, then fold the
    // exclusive partial into g_bins and zero it (exclusive -> safe).
    __threadfence();
    __syncthreads();
    if (tid < NBINS) {
        float t = __ldcg(&mypart[tid]);
        atomicAdd(&g_bins[img][tid], t);
        mypart[tid] = 0.0f;
    }

    // ---- last-block-done: finalize inline ----
    if (tid == 0) {
        __threadfence();
        unsigned int tk = atomicAdd(&g_ticket, 1u);
        s_last = (tk == TOTAL_BLOCKS - 1);
    }
    __syncthreads();
    if (!s_last) return;

    // All blocks' atomics visible (threadfence-before-ticket). Read via L2.
    #pragma unroll
    for (int c = 0; c < 2; c++) {
        int k = tid + c * TPB;
        if (k < NIMG * NBINS)
            ((float*)binc)[k] = __ldcg(&((const float*)g_bins)[k]);
    }
    __syncthreads();

    if (tid < NIMG) {
        const float* b = binc[tid];

        // pred_area[p] = sum_l inter[l][p]
        float pa[PBINS];
        #pragma unroll
        for (int p = 0; p < PBINS; p++) {
            float sum = 0.0f;
            #pragma unroll
            for (int l = 0; l < LBINS; l++) sum += b[l * PBINS + p];
            pa[p] = sum;
        }

        bool colnz[PBINS];
        #pragma unroll
        for (int p = 0; p < PBINS; p++) colnz[p] = false;

        float pair_conn_sum = 0.0f;
        #pragma unroll
        for (int l = 1; l < LBINS; l++) {
            float la = b[60 + l];
            float pc = 0.0f;
            int   pn = 0;
            #pragma unroll
            for (int p = 1; p < PBINS; p++) {
                float in = b[l * PBINS + p];
                if (in != 0.0f) {
                    float uni = la + pa[p] - in;
                    pc += in / uni;
                    pn++;
                    colnz[p] = true;
                }
            }
            if (pn > 0) pair_conn_sum += pc / (float)pn;
        }

        int lone = 0;
        #pragma unroll
        for (int p = 1; p < PBINS; p++) if (!colnz[p]) lone++;

        float denom = (float)(LBINS - 1) + (float)lone;
        losses[tid] = 1.0f - pair_conn_sum / denom;
    }
    __syncthreads();

    if (tid == 0)
        out[0] = (losses[0] + losses[1] + losses[2] + losses[3]) * 0.25f;

    // Restore shared scratch for the next (graph-replayed) call.
    #pragma unroll
    for (int c = 0; c < 2; c++) {
        int k = tid + c * TPB;
        if (k < NIMG * NBINS) ((float*)g_bins)[k] = 0.0f;
    }
    if (tid == 0) g_ticket = 0u;
}

extern "C" void kernel_launch(void* const* d_in, const int* in_sizes, int n_in,
                              void* d_out, int out_size) {
    const float* pred  = (const float*)d_in[0];
    const int*   pconn = (const int*)d_in[1];
    const int*   lconn = (const int*)d_in[2];
    float* out = (float*)d_out;

    dim3 grid(BLOCKS_PER_IMG, NIMG);
    sc_fused_kernel<<<grid, TPB>>>(pred, pconn, lconn, out);
}

// round 13
// speedup vs baseline: 1.5153x; 1.5153x over previous
#include <cuda_runtime.h>
#include <cstdint>

#define NIMG 4
#define PBINS 10
#define LBINS 6
#define NBINS 66                      // 60 inter bins + 6 label-count bins
#define TPB 256
#define NWARPS (TPB/32)               // 8
#define BLOCKS_PER_IMG 148            // 592 blocks = exactly 4 per SM
#define TOTAL_BLOCKS (BLOCKS_PER_IMG * NIMG)
#define VECS_PER_IMG (1024*1024/4)    // 262144 float4 per image
#define STRIDE (BLOCKS_PER_IMG * TPB) // 37888
#define KITERS 7                      // 7*37888 >= 262144 (guarded)

// Global scratch (zero-initialized at module load; every block restores its
// own slice before exit, so graph replays see identical state).
__device__ float g_part[TOTAL_BLOCKS][64];     // per-block exclusive partials
__device__ float g_bins[NIMG][NBINS];
__device__ unsigned int g_ticket;

__global__ void __launch_bounds__(TPB, 4)
sc_fused_kernel(const float* __restrict__ pred,
                const int* __restrict__ pconn,
                const int* __restrict__ lconn,
                float* __restrict__ out) {
    // Scatter split across TWO independent RMW units:
    //   x,y,z -> per-warp smem ATOMS (SM atomic unit, ~12us capacity)
    //   w     -> fire-and-forget REDG into this block's exclusive global
    //            partial (L2 atomic ALUs, ~6us at 1/4 rate, runs in parallel)
    __shared__ float whist[NWARPS][64];
    __shared__ float scnt[LBINS];
    __shared__ float losses[NIMG];
    __shared__ float binc[NIMG][NBINS];
    __shared__ bool  s_last;

    const int tid  = threadIdx.x;
    const int lane = tid & 31;
    const int wid  = tid >> 5;
    const int img  = blockIdx.y;
    const int bid  = blockIdx.y * BLOCKS_PER_IMG + blockIdx.x;

    #pragma unroll
    for (int k = tid; k < NWARPS * 64; k += TPB) ((float*)whist)[k] = 0.0f;
    if (tid < LBINS) scnt[tid] = 0.0f;
    __syncthreads();

    const size_t base = (size_t)img * VECS_PER_IMG;
    const float4* __restrict__ p4  = ((const float4*)pred)  + base;
    const int4*   __restrict__ pc4 = ((const int4*)pconn)   + base;
    const int4*   __restrict__ lc4 = ((const int4*)lconn)   + base;

    float* const myhist = whist[wid];
    float* const mypart = g_part[bid];

    // Label counts: 6 byte-fields packed in a 64-bit register.
    // <= 28 pixels/thread -> fields never overflow 8 bits.
    unsigned long long cnt = 0ULL;

    int v = blockIdx.x * TPB + tid;
    #pragma unroll
    for (int k = 0; k < KITERS; k++, v += STRIDE) {
        if (v < VECS_PER_IMG) {
            float4 p = p4[v];
            int4   c = pc4[v];
            int4   l = lc4[v];
            atomicAdd(&myhist[l.x * PBINS + c.x], p.x);   // smem unit
            atomicAdd(&myhist[l.y * PBINS + c.y], p.y);   // smem unit
            atomicAdd(&myhist[l.z * PBINS + c.z], p.z);   // smem unit
            atomicAdd(&mypart[l.w * PBINS + c.w], p.w);   // L2 unit (RED)
            cnt += (1ULL << (8 * l.x)) + (1ULL << (8 * l.y))
                 + (1ULL << (8 * l.z)) + (1ULL << (8 * l.w));
        }
    }

    // Warp-reduce packed counts. Split 8-bit fields into two words of
    // 16-bit-spaced fields so sums over 32 lanes (<=896) don't overflow.
    unsigned long long lo = cnt & 0x00FF00FF00FF00FFULL;         // labels 0,2,4
    unsigned long long hi = (cnt >> 8) & 0x00FF00FF00FF00FFULL;  // labels 1,3,5
    #pragma unroll
    for (int d = 16; d > 0; d >>= 1) {
        lo += __shfl_down_sync(0xFFFFFFFFu, lo, d);
        hi += __shfl_down_sync(0xFFFFFFFFu, hi, d);
    }
    if (lane == 0) {
        #pragma unroll
        for (int l = 0; l < 3; l++) {
            atomicAdd(&scnt[2 * l],     (float)((lo >> (16 * l)) & 0xFFFFULL));
            atomicAdd(&scnt[2 * l + 1], (float)((hi >> (16 * l)) & 0xFFFFULL));
        }
    }

    // Own REDGs must be visible before reading mypart back.
    __threadfence();
    __syncthreads();

    // Fold 8 warp-histograms + own global partial + counts into g_bins,
    // and zero the exclusive partial (safe: no other block touches it).
    if (tid < 60) {
        float t = __ldcg(&mypart[tid]);
        #pragma unroll
        for (int w = 0; w < NWARPS; w++) t += whist[w][tid];
        atomicAdd(&g_bins[img][tid], t);
        mypart[tid] = 0.0f;
    } else if (tid < NBINS) {
        atomicAdd(&g_bins[img][tid], scnt[tid - 60]);
    }

    // ---- last-block-done: finalize inline ----
    if (tid == 0) {
        __threadfence();
        unsigned int tk = atomicAdd(&g_ticket, 1u);
        s_last = (tk == TOTAL_BLOCKS - 1);
    }
    __syncthreads();
    if (!s_last) return;

    // All blocks' atomics visible (threadfence-before-ticket). Read via L2.
    #pragma unroll
    for (int c = 0; c < 2; c++) {
        int k = tid + c * TPB;
        if (k < NIMG * NBINS)
            ((float*)binc)[k] = __ldcg(&((const float*)g_bins)[k]);
    }
    __syncthreads();

    if (tid < NIMG) {
        const float* b = binc[tid];

        // pred_area[p] = sum_l inter[l][p]
        float pa[PBINS];
        #pragma unroll
        for (int p = 0; p < PBINS; p++) {
            float sum = 0.0f;
            #pragma unroll
            for (int l = 0; l < LBINS; l++) sum += b[l * PBINS + p];
            pa[p] = sum;
        }

        bool colnz[PBINS];
        #pragma unroll
        for (int p = 0; p < PBINS; p++) colnz[p] = false;

        float pair_conn_sum = 0.0f;
        #pragma unroll
        for (int l = 1; l < LBINS; l++) {
            float la = b[60 + l];
            float pc = 0.0f;
            int   pn = 0;
            #pragma unroll
            for (int p = 1; p < PBINS; p++) {
                float in = b[l * PBINS + p];
                if (in != 0.0f) {
                    float uni = la + pa[p] - in;
                    pc += in / uni;
                    pn++;
                    colnz[p] = true;
                }
            }
            if (pn > 0) pair_conn_sum += pc / (float)pn;
        }

        int lone = 0;
        #pragma unroll
        for (int p = 1; p < PBINS; p++) if (!colnz[p]) lone++;

        float denom = (float)(LBINS - 1) + (float)lone;
        losses[tid] = 1.0f - pair_conn_sum / denom;
    }
    __syncthreads();

    if (tid == 0)
        out[0] = (losses[0] + losses[1] + losses[2] + losses[3]) * 0.25f;

    // Restore shared scratch for the next (graph-replayed) call.
    #pragma unroll
    for (int c = 0; c < 2; c++) {
        int k = tid + c * TPB;
        if (k < NIMG * NBINS) ((float*)g_bins)[k] = 0.0f;
    }
    if (tid == 0) g_ticket = 0u;
}

extern "C" void kernel_launch(void* const* d_in, const int* in_sizes, int n_in,
                              void* d_out, int out_size) {
    const float* pred  = (const float*)d_in[0];
    const int*   pconn = (const int*)d_in[1];
    const int*   lconn = (const int*)d_in[2];
    float* out = (float*)d_out;

    dim3 grid(BLOCKS_PER_IMG, NIMG);
    sc_fused_kernel<<<grid, TPB>>>(pred, pconn, lconn, out);
}

// round 15
// speedup vs baseline: 1.6611x; 1.0962x over previous
#include <cuda_runtime.h>
#include <cstdint>

#define NIMG 4
#define PBINS 10
#define LBINS 6
#define NBINS 66                      // 60 inter bins + 6 label-count bins
#define TPB 256
#define NWARPS (TPB/32)               // 8
#define BLOCKS_PER_IMG 148            // 592 blocks = exactly 4 per SM
#define TOTAL_BLOCKS (BLOCKS_PER_IMG * NIMG)
#define VECS_PER_IMG (1024*1024/4)    // 262144 float4 per image
#define STRIDE (BLOCKS_PER_IMG * TPB) // 37888
// 6 full iterations are always in range (max v = 227327 < 262144);
// the 7th is guarded.

// Global scratch (zero-initialized at module load; kernel restores zeros
// before exit so every graph replay sees identical state).
__device__ float g_bins[NIMG][NBINS];
__device__ unsigned int g_ticket;

__device__ __forceinline__ uint32_t smem_u32(const void* p) {
    uint32_t a;
    asm("{ .reg .u64 t; cvta.to.shared.u64 t, %1; cvt.u32.u64 %0, t; }"
        : "=r"(a) : "l"(p));
    return a;
}

// Branch-free predicated shared-memory reduction: lanes with cnd==0 issue
// NO atomic request and NO branch (C++ `if` would emit BSSY/BSYNC, 33-56cyc).
// No memory clobber: operand deps order it; loads may pipeline around it.
#define REDS_IF(cnd, addr, val)                                          \
    asm volatile("{ .reg .pred p; setp.ne.s32 p, %0, 0;"                 \
                 "  @p red.shared.add.f32 [%1], %2; }"                   \
                 :: "r"(cnd), "r"(addr), "f"(val))

__global__ void __launch_bounds__(TPB, 4)
sc_fused_kernel(const float* __restrict__ pred,
                const int* __restrict__ pconn,
                const int* __restrict__ lconn,
                float* __restrict__ out) {
    // Per-WARP shared histograms (2 KB) -> tiny smem, 4 blocks/SM resident.
    __shared__ float whist[NWARPS][64];
    __shared__ float scnt[LBINS];
    __shared__ float losses[NIMG];
    __shared__ float binc[NIMG][NBINS];
    __shared__ bool  s_last;

    const int tid  = threadIdx.x;
    const int lane = tid & 31;
    const int wid  = tid >> 5;
    const int img  = blockIdx.y;

    #pragma unroll
    for (int k = tid; k < NWARPS * 64; k += TPB) ((float*)whist)[k] = 0.0f;
    if (tid < LBINS) scnt[tid] = 0.0f;
    __syncthreads();

    const size_t base = (size_t)img * VECS_PER_IMG;
    const float4* __restrict__ p4  = ((const float4*)pred)  + base;
    const int4*   __restrict__ pc4 = ((const int4*)pconn)   + base;
    const int4*   __restrict__ lc4 = ((const int4*)lconn)   + base;

    const uint32_t hbase = smem_u32(&whist[wid][0]);

    // Label counts: 6 byte-fields packed in a 64-bit register.
    // <= 28 pixels/thread -> fields never overflow 8 bits.
    unsigned long long cnt = 0ULL;

    int v = blockIdx.x * TPB + tid;
    #pragma unroll
    for (int k = 0; k < 6; k++, v += STRIDE) {
        float4 p = p4[v];
        int4   c = pc4[v];
        int4   l = lc4[v];
        // Skip p==0 bins entirely (10% of lane-ops): inter[l][0] is never
        // read by the finalize (all consumer loops are p>=1).
        REDS_IF(c.x, hbase + (uint32_t)(l.x * PBINS + c.x) * 4u, p.x);
        REDS_IF(c.y, hbase + (uint32_t)(l.y * PBINS + c.y) * 4u, p.y);
        REDS_IF(c.z, hbase + (uint32_t)(l.z * PBINS + c.z) * 4u, p.z);
        REDS_IF(c.w, hbase + (uint32_t)(l.w * PBINS + c.w) * 4u, p.w);
        cnt += (1ULL << (8 * l.x)) + (1ULL << (8 * l.y))
             + (1ULL << (8 * l.z)) + (1ULL << (8 * l.w));
    }
    if (v < VECS_PER_IMG) {              // guarded 7th iteration only
        float4 p = p4[v];
        int4   c = pc4[v];
        int4   l = lc4[v];
        REDS_IF(c.x, hbase + (uint32_t)(l.x * PBINS + c.x) * 4u, p.x);
        REDS_IF(c.y, hbase + (uint32_t)(l.y * PBINS + c.y) * 4u, p.y);
        REDS_IF(c.z, hbase + (uint32_t)(l.z * PBINS + c.z) * 4u, p.z);
        REDS_IF(c.w, hbase + (uint32_t)(l.w * PBINS + c.w) * 4u, p.w);
        cnt += (1ULL << (8 * l.x)) + (1ULL << (8 * l.y))
             + (1ULL << (8 * l.z)) + (1ULL << (8 * l.w));
    }

    // Warp-reduce packed counts. Split 8-bit fields into two words of
    // 16-bit-spaced fields so sums over 32 lanes (<=896) don't overflow.
    unsigned long long lo = cnt & 0x00FF00FF00FF00FFULL;         // labels 0,2,4
    unsigned long long hi = (cnt >> 8) & 0x00FF00FF00FF00FFULL;  // labels 1,3,5
    #pragma unroll
    for (int d = 16; d > 0; d >>= 1) {
        lo += __shfl_down_sync(0xFFFFFFFFu, lo, d);
        hi += __shfl_down_sync(0xFFFFFFFFu, hi, d);
    }
    if (lane == 0) {
        #pragma unroll
        for (int l = 0; l < 3; l++) {
            atomicAdd(&scnt[2 * l],     (float)((lo >> (16 * l)) & 0xFFFFULL));
            atomicAdd(&scnt[2 * l + 1], (float)((hi >> (16 * l)) & 0xFFFFULL));
        }
    }
    __syncthreads();

    // Fold 8 warp-histograms + counts into global bins.
    if (tid < 60) {
        float t = 0.0f;
        #pragma unroll
        for (int w = 0; w < NWARPS; w++) t += whist[w][tid];
        atomicAdd(&g_bins[img][tid], t);
    } else if (tid < NBINS) {
        atomicAdd(&g_bins[img][tid], scnt[tid - 60]);
    }

    // ---- last-block-done: finalize inline, then restore scratch to zero ----
    if (tid == 0) {
        __threadfence();
        unsigned int tk = atomicAdd(&g_ticket, 1u);
        s_last = (tk == TOTAL_BLOCKS - 1);
    }
    __syncthreads();
    if (!s_last) return;

    // All blocks' atomics visible (threadfence-before-ticket). Read via L2.
    #pragma unroll
    for (int c = 0; c < 2; c++) {
        int k = tid + c * TPB;
        if (k < NIMG * NBINS)
            ((float*)binc)[k] = __ldcg(&((const float*)g_bins)[k]);
    }
    __syncthreads();

    if (tid < NIMG) {
        const float* b = binc[tid];

        // pred_area[p] = sum_l inter[l][p]  (p>=1 only is ever used)
        float pa[PBINS];
        #pragma unroll
        for (int p = 0; p < PBINS; p++) {
            float sum = 0.0f;
            #pragma unroll
            for (int l = 0; l < LBINS; l++) sum += b[l * PBINS + p];
            pa[p] = sum;
        }

        bool colnz[PBINS];
        #pragma unroll
        for (int p = 0; p < PBINS; p++) colnz[p] = false;

        float pair_conn_sum = 0.0f;
        #pragma unroll
        for (int l = 1; l < LBINS; l++) {
            float la = b[60 + l];
            float pc = 0.0f;
            int   pn = 0;
            #pragma unroll
            for (int p = 1; p < PBINS; p++) {
                float in = b[l * PBINS + p];
                if (in != 0.0f) {
                    float uni = la + pa[p] - in;
                    pc += in / uni;
                    pn++;
                    colnz[p] = true;
                }
            }
            if (pn > 0) pair_conn_sum += pc / (float)pn;
        }

        int lone = 0;
        #pragma unroll
        for (int p = 1; p < PBINS; p++) if (!colnz[p]) lone++;

        float denom = (float)(LBINS - 1) + (float)lone;
        losses[tid] = 1.0f - pair_conn_sum / denom;
    }
    __syncthreads();

    if (tid == 0)
        out[0] = (losses[0] + losses[1] + losses[2] + losses[3]) * 0.25f;

    // Restore scratch to zero for the next (graph-replayed) call.
    #pragma unroll
    for (int c = 0; c < 2; c++) {
        int k = tid + c * TPB;
        if (k < NIMG * NBINS) ((float*)g_bins)[k] = 0.0f;
    }
    if (tid == 0) g_ticket = 0u;
}

extern "C" void kernel_launch(void* const* d_in, const int* in_sizes, int n_in,
                              void* d_out, int out_size) {
    const float* pred  = (const float*)d_in[0];
    const int*   pconn = (const int*)d_in[1];
    const int*   lconn = (const int*)d_in[2];
    float* out = (float*)d_out;

    dim3 grid(BLOCKS_PER_IMG, NIMG);
    sc_fused_kernel<<<grid, TPB>>>(pred, pconn, lconn, out);
}